// round 12
// baseline (speedup 1.0000x reference)
#include <cuda_runtime.h>
#include <cuda_bf16.h>
#include <math.h>

// ---------------------------------------------------------------------------
// PhysicsAwareMSELoss — ONE fused kernel, 32 blocks total.
//   stats blocks (16): ONE WARP PER SAMPLE (8 warps/block). Warp streams its
//                      row (strided float4, unroll 4), shuffle-reduces 7 sums,
//                      lane 0 finishes per-sample math -> g_samp[4][b].
//                      Scalars (mat[b], E[b], w[0..nW)) prefetched at warp
//                      start into lanes; selected later via shuffle (no
//                      dependent-load tail). No smem, no syncthreads in path.
//   strip blocks (16): 1024 pairs each; 4 screens/thread; deterministic scan
//                      compaction; survivors dealt to 8 warps; per-pair
//                      lane-strided float4 reduce (unroll 8) -> g_pairAcc.
//   sync: thread 0 per block: atom.add.acq_rel.gpu (32 atomics total).
//         Last block sums partials via __ldcg -> out[0], resets ticket.
// ---------------------------------------------------------------------------

#define MAXB    256
#define MAXSTRP 64
#define ALPHA   0.7f
#define BETA    0.3f
#define STRIP   1024    // pairs per strip block (256 thr x 4)

__device__ float g_samp[4][MAXB];          // 0:wmse 1:el_err 2:el_valid 3:mono
__device__ float g_pairAcc[4][MAXSTRP];    // 0:tsum 1:tcnt 2:ssum 3:scnt
__device__ unsigned int g_ticket;          // zero-init; reset by last block

__device__ __forceinline__ float reluf(float x) { return fmaxf(x, 0.f); }

__device__ __forceinline__ unsigned int ticket_add_acq_rel(unsigned int* p)
{
    unsigned int old;
    asm volatile("atom.add.acq_rel.gpu.u32 %0, [%1], 1;"
                 : "=r"(old) : "l"(p) : "memory");
    return old;
}

__device__ __forceinline__ void pair_masks(int mi, int mj,
                                           float sri, float srj,
                                           float ti, float tj,
                                           bool& tmask_ij, bool& smask_ij)
{
    bool same   = (mi == mj);
    float hi    = fmaxf(sri, srj);
    float lo    = fminf(sri, srj);
    float ratio = hi / (lo + 1e-8f);
    float tdiff = ti - tj;
    tmask_ij = same && (ratio <= 1.2f) && (fabsf(tdiff) >= 10.f) && (tdiff > 0.f);
    smask_ij = same && (fabsf(tdiff) <= 10.f) && (ratio >= 1.2f) && (sri > srj);
}

__global__ void __launch_bounds__(256)
fused_kernel(const float* __restrict__ pred,
             const float* __restrict__ target,
             const int*   __restrict__ mat,
             const float* __restrict__ strain,
             const float* __restrict__ E,
             const float* __restrict__ temp,
             const float* __restrict__ sr,
             const float* __restrict__ w,
             float* __restrict__ out,
             int B, int S, int nStats, int nStrips, int nW)
{
    const int tid  = threadIdx.x;
    const int lane = tid & 31;
    const int wid  = tid >> 5;
    const unsigned FULL = 0xFFFFFFFFu;

    __shared__ float sh[8][8];
    __shared__ bool  sh_last;

    if (blockIdx.x < (unsigned)nStats) {
        // ------------- warp-per-sample stats: no smem, no block sync -------------
        const int b = blockIdx.x * 8 + wid;
        if (b < B) {
            // prefetch scalars into lanes (issued now, consumed after the loop)
            float wl  = (lane < nW) ? w[lane] : 0.f;
            int   mbl = (lane == 0) ? mat[b] : 0;
            float Ebl = (lane == 0) ? E[b]   : 0.f;

            const float*  p  = pred   + (size_t)b * S;
            const float4* P4 = reinterpret_cast<const float4*>(p);
            const float4* T4 = reinterpret_cast<const float4*>(target + (size_t)b * S);
            const float4* E4 = reinterpret_cast<const float4*>(strain + (size_t)b * S);

            float v0=0.f,v1=0.f,v2=0.f,v3=0.f,v4=0.f,v5=0.f,v6=0.f;
            const int S4     = S >> 2;
            const int rounds = (S4 + 31) >> 5;

            #pragma unroll 4
            for (int r = 0; r < rounds; r++) {
                const int it = r * 32 + lane;
                const bool ok = (it < S4);
                float4 pv, tv, ev;
                if (ok) { pv = P4[it]; tv = T4[it]; ev = E4[it]; }
                else    { pv = make_float4(0,0,0,0); tv = pv; ev = make_float4(1,1,1,1); }

                // shuffle executed by all lanes (uniform)
                float nxt = __shfl_down_sync(FULL, pv.x, 1);

                if (ok) {
                    float dx = pv.x - tv.x, dy = pv.y - tv.y,
                          dz = pv.z - tv.z, dw = pv.w - tv.w;
                    v0 += dx*dx + dy*dy + dz*dz + dw*dw;

                    if (ev.x < 0.02f) { v1 += 1.f; v2 += ev.x; v3 += pv.x; v4 += ev.x*pv.x; v5 += ev.x*ev.x; }
                    if (ev.y < 0.02f) { v1 += 1.f; v2 += ev.y; v3 += pv.y; v4 += ev.y*pv.y; v5 += ev.y*ev.y; }
                    if (ev.z < 0.02f) { v1 += 1.f; v2 += ev.z; v3 += pv.z; v4 += ev.z*pv.z; v5 += ev.z*ev.z; }
                    if (ev.w < 0.02f) { v1 += 1.f; v2 += ev.w; v3 += pv.w; v4 += ev.w*pv.w; v5 += ev.w*ev.w; }

                    v6 += reluf(pv.x - pv.y) + reluf(pv.y - pv.z) + reluf(pv.z - pv.w);
                    if (4 * it + 4 < S) {
                        if (lane == 31) nxt = p[4 * it + 4];
                        v6 += reluf(pv.w - nxt);
                    }
                }
            }

            // warp shuffle reduce (fixed order, deterministic)
            #pragma unroll
            for (int off = 16; off > 0; off >>= 1) {
                v0 += __shfl_xor_sync(FULL, v0, off);
                v1 += __shfl_xor_sync(FULL, v1, off);
                v2 += __shfl_xor_sync(FULL, v2, off);
                v3 += __shfl_xor_sync(FULL, v3, off);
                v4 += __shfl_xor_sync(FULL, v4, off);
                v5 += __shfl_xor_sync(FULL, v5, off);
                v6 += __shfl_xor_sync(FULL, v6, off);
            }

            // scalar select from prefetched lanes (no memory access)
            const int   mb   = __shfl_sync(FULL, mbl, 0);
            const float Eb   = __shfl_sync(FULL, Ebl, 0);
            const float wsel = __shfl_sync(FULL, wl, mb & 31);

            if (lane == 0) {
                float wmse = (v0 / (float)S) * wsel;
                float el_err = 0.f, el_valid = 0.f;
                if (v1 >= 2.f) {
                    float safe  = fmaxf(v1, 1.f);
                    float eps_m = v2 / safe;
                    float sig_m = v3 / safe;
                    float cov = v4 - sig_m * v2 - eps_m * v3 + v1 * eps_m * sig_m;
                    float var = v5 - 2.f * eps_m * v2 + v1 * eps_m * eps_m;
                    float et  = Eb * 1000.f;
                    el_err   = fabsf(cov / (var + 1e-8f) - et) / (et + 1e-8f);
                    el_valid = 1.f;
                }
                g_samp[0][b] = wmse;
                g_samp[1][b] = el_err;
                g_samp[2][b] = el_valid;
                g_samp[3][b] = v6;
            }
        }
    } else {
        // ------- strip block: 1024 pairs; screen x4, scan-compact, balanced reduce -------
        __shared__ int   s_mat[MAXB];
        __shared__ float s_sr[MAXB];
        __shared__ float s_temp[MAXB];
        __shared__ int   s_list[STRIP];
        __shared__ int   s_wsum[8];
        __shared__ int   s_wbase[8];
        __shared__ int   s_total;

        const int strip = blockIdx.x - nStats;
        const int totalPairs = B * B;
        const int base = strip * STRIP;

        for (int q = tid; q < B; q += 256) {
            s_mat[q]  = mat[q];
            s_sr[q]   = sr[q];
            s_temp[q] = temp[q];
        }
        __syncthreads();

        bool nt[4], ns[4];
        int  c = 0;
        #pragma unroll
        for (int q = 0; q < 4; q++) {
            nt[q] = false; ns[q] = false;
            const int idx = base + tid * 4 + q;
            if (idx < totalPairs) {
                const int i = idx / B;
                const int j = idx - i * B;
                if (i != j) {
                    bool sd, td;
                    pair_masks(s_mat[i], s_mat[j], s_sr[i], s_sr[j],
                               s_temp[i], s_temp[j], nt[q], sd);
                    pair_masks(s_mat[j], s_mat[i], s_sr[j], s_sr[i],
                               s_temp[j], s_temp[i], td, ns[q]);
                }
            }
            if (nt[q] || ns[q]) c++;
        }

        int x = c;
        #pragma unroll
        for (int off = 1; off < 32; off <<= 1) {
            int y = __shfl_up_sync(FULL, x, off);
            if (lane >= off) x += y;
        }
        if (lane == 31) s_wsum[wid] = x;
        __syncthreads();
        if (tid == 0) {
            int run = 0;
            #pragma unroll
            for (int q = 0; q < 8; q++) { s_wbase[q] = run; run += s_wsum[q]; }
            s_total = run;
        }
        __syncthreads();
        {
            int pos = s_wbase[wid] + x - c;
            #pragma unroll
            for (int q = 0; q < 4; q++) {
                if (nt[q] || ns[q])
                    s_list[pos++] = ((tid * 4 + q) << 2) | ((int)nt[q] << 1) | (int)ns[q];
            }
        }
        __syncthreads();

        const int total = s_total;
        float tsum = 0.f, tcnt = 0.f, ssum = 0.f, scnt = 0.f;
        const int S4 = S >> 2;
        for (int li = wid; li < total; li += 8) {
            const int packed = s_list[li];
            const int pidx   = base + (packed >> 2);
            const int tt     = (packed >> 1) & 1;
            const int ss     = packed & 1;
            const int i = pidx / B;
            const int j = pidx - i * B;

            const float4* si = reinterpret_cast<const float4*>(pred + (size_t)i * S);
            const float4* sj = reinterpret_cast<const float4*>(pred + (size_t)j * S);
            float acc = 0.f;
            #pragma unroll 8
            for (int k = lane; k < S4; k += 32) {
                float4 a = si[k], bq = sj[k];
                acc += reluf(a.x - bq.x) + reluf(a.y - bq.y)
                     + reluf(a.z - bq.z) + reluf(a.w - bq.w);
            }
            #pragma unroll
            for (int off = 16; off > 0; off >>= 1)
                acc += __shfl_xor_sync(FULL, acc, off);
            const float D = acc / (float)S;
            if (tt) { tsum += D; tcnt += 1.f; }
            if (ss) { ssum += D; scnt += 1.f; }
        }

        if (lane == 0) {
            sh[0][wid] = tsum; sh[1][wid] = tcnt;
            sh[2][wid] = ssum; sh[3][wid] = scnt;
        }
        __syncthreads();
        if (tid == 0) {
            float r0 = 0.f, r1 = 0.f, r2 = 0.f, r3 = 0.f;
            #pragma unroll
            for (int q = 0; q < 8; q++) {
                r0 += sh[0][q]; r1 += sh[1][q];
                r2 += sh[2][q]; r3 += sh[3][q];
            }
            g_pairAcc[0][strip] = r0;
            g_pairAcc[1][strip] = r1;
            g_pairAcc[2][strip] = r2;
            g_pairAcc[3][strip] = r3;
        }
    }

    // ============ sync: bar + one scoped atomic per block (32 total) ============
    __syncthreads();   // orders all warps' global writes before thread 0's release
    if (tid == 0) {
        unsigned int vtk = ticket_add_acq_rel(&g_ticket);
        sh_last = (vtk == gridDim.x - 1);
    }
    __syncthreads();
    if (!sh_last) return;

    // ---- last block: sum partials (L2-direct), write scalar ----
    float acc8[8];
    #pragma unroll
    for (int k = 0; k < 8; k++) acc8[k] = 0.f;

    for (int q = tid; q < B; q += 256) {
        acc8[0] += __ldcg(&g_samp[0][q]);
        acc8[1] += __ldcg(&g_samp[1][q]);
        acc8[2] += __ldcg(&g_samp[2][q]);
        acc8[3] += __ldcg(&g_samp[3][q]);
    }
    for (int s = tid; s < nStrips; s += 256) {
        acc8[4] += __ldcg(&g_pairAcc[0][s]);
        acc8[5] += __ldcg(&g_pairAcc[1][s]);
        acc8[6] += __ldcg(&g_pairAcc[2][s]);
        acc8[7] += __ldcg(&g_pairAcc[3][s]);
    }

    #pragma unroll
    for (int k = 0; k < 8; k++) {
        #pragma unroll
        for (int off = 16; off > 0; off >>= 1)
            acc8[k] += __shfl_xor_sync(FULL, acc8[k], off);
    }
    __syncthreads();
    if (lane == 0) {
        #pragma unroll
        for (int k = 0; k < 8; k++) sh[k][wid] = acc8[k];
    }
    __syncthreads();
    if (tid == 0) {
        float r[8];
        #pragma unroll
        for (int k = 0; k < 8; k++) {
            r[k] = 0.f;
            #pragma unroll
            for (int q = 0; q < 8; q++) r[k] += sh[k][q];
        }
        float mse_loss  = r[0] / (float)B;
        float elastic   = (r[2] > 0.f) ? r[1] / fmaxf(r[2], 1.f) : 0.f;
        float mono      = r[3] / (float)(B * (S - 1));
        float temp_loss = (r[5] > 0.f) ? r[4] / fmaxf(r[5], 1.f) : 0.f;
        float sr_loss   = (r[7] > 0.f) ? r[6] / fmaxf(r[7], 1.f) : 0.f;
        out[0] = ALPHA * mse_loss + BETA * (elastic + mono + temp_loss + sr_loss);
        g_ticket = 0;   // reset for next graph replay
    }
}

// --------------------------------------------------------------------------
extern "C" void kernel_launch(void* const* d_in, const int* in_sizes, int n_in,
                              void* d_out, int out_size)
{
    const float* pred   = (const float*)d_in[0];
    const float* target = (const float*)d_in[1];
    const int*   matid  = (const int*)  d_in[2];
    const float* strain = (const float*)d_in[3];
    const float* E_GPa  = (const float*)d_in[4];
    const float* temp   = (const float*)d_in[5];
    const float* sr     = (const float*)d_in[6];
    const float* mw     = (const float*)d_in[7];
    float* out = (float*)d_out;

    const int B  = in_sizes[2];         // material_ids count
    const int S  = in_sizes[0] / B;     // pred = B*S
    const int nW = in_sizes[7];         // material_weights count

    const int nStats  = (B + 7) / 8;                     // 16 for B=128
    const int nStrips = (B * B + STRIP - 1) / STRIP;     // 16 for B=128
    const int grid    = nStats + nStrips;                // 32 blocks

    fused_kernel<<<grid, 256>>>(pred, target, matid, strain, E_GPa, temp, sr, mw,
                                out, B, S, nStats, nStrips, nW);
}

// round 13
// speedup vs baseline: 1.3528x; 1.3528x over previous
#include <cuda_runtime.h>
#include <cuda_bf16.h>
#include <math.h>

// ---------------------------------------------------------------------------
// PhysicsAwareMSELoss — ONE fused kernel (round-9 architecture + scalar
// prefetch). grid = B stats blocks + 64 strip blocks = 192.
//   stats blocks (B): 256 thr x 8 elems (2x float4 per array, 1 load round);
//                     scalars (w[], mat[b], E[b]) prefetched at block start
//                     under the row-load shadow; block reduces 7 sums;
//                     thread 0 finishes per-sample math -> g_samp[4][b].
//   strip blocks (64): 256 pairs; 1 screen/thread (smem scalars); ballot+
//                     prefix compaction (deterministic); survivors dealt
//                     round-robin to 8 warps; per-pair lane-strided float4
//                     reduce (unroll 8) -> g_pairAcc[4][strip].
//   sync: thread 0 per block: atom.add.acq_rel.gpu (no MEMBAR anywhere).
//         Last block sums 768 partials via __ldcg -> out[0], resets ticket.
// ---------------------------------------------------------------------------

#define MAXB    256
#define MAXSTRP 256
#define ALPHA   0.7f
#define BETA    0.3f
#define STRIP   256     // pairs per strip block

__device__ float g_samp[4][MAXB];        // 0:wmse 1:el_err 2:el_valid 3:mono
__device__ float g_pairAcc[4][MAXSTRP];  // 0:tsum 1:tcnt 2:ssum 3:scnt
__device__ unsigned int g_ticket;        // zero-init; reset by last block

__device__ __forceinline__ float reluf(float x) { return fmaxf(x, 0.f); }

__device__ __forceinline__ unsigned int ticket_add_acq_rel(unsigned int* p)
{
    unsigned int old;
    asm volatile("atom.add.acq_rel.gpu.u32 %0, [%1], 1;"
                 : "=r"(old) : "l"(p) : "memory");
    return old;
}

__device__ __forceinline__ void pair_masks(int mi, int mj,
                                           float sri, float srj,
                                           float ti, float tj,
                                           bool& tmask_ij, bool& smask_ij)
{
    bool same   = (mi == mj);
    float hi    = fmaxf(sri, srj);
    float lo    = fminf(sri, srj);
    float ratio = hi / (lo + 1e-8f);
    float tdiff = ti - tj;
    tmask_ij = same && (ratio <= 1.2f) && (fabsf(tdiff) >= 10.f) && (tdiff > 0.f);
    smask_ij = same && (fabsf(tdiff) <= 10.f) && (ratio >= 1.2f) && (sri > srj);
}

__global__ void __launch_bounds__(256)
fused_kernel(const float* __restrict__ pred,
             const float* __restrict__ target,
             const int*   __restrict__ mat,
             const float* __restrict__ strain,
             const float* __restrict__ E,
             const float* __restrict__ temp,
             const float* __restrict__ sr,
             const float* __restrict__ w,
             float* __restrict__ out,
             int B, int S, int nStrips, int nW)
{
    const int tid  = threadIdx.x;
    const int lane = tid & 31;
    const int wid  = tid >> 5;
    const unsigned FULL = 0xFFFFFFFFu;

    __shared__ float sh[8][8];
    __shared__ bool  sh_last;

    if (blockIdx.x < (unsigned)B) {
        // ---------------- one block per sample: stats + per-sample math ----------
        const int b = blockIdx.x;

        // scalar prefetch: issued before the row loads, consumed after reduce.
        // warp 0 lanes hold w[]; lane0 of warp 0 holds mat[b], E[b].
        float wl = 0.f; int mbl = 0; float Ebl = 0.f;
        if (wid == 0) {
            if (lane < nW) wl = w[lane];
            if (lane == 0) { mbl = mat[b]; Ebl = E[b]; }
        }

        const float* p = pred   + (size_t)b * S;
        const float* t = target + (size_t)b * S;
        const float* e = strain + (size_t)b * S;

        float v[7];   // d2, cnt, sx, sy, sxy, sxx, mono
        #pragma unroll
        for (int k = 0; k < 7; k++) v[k] = 0.f;

        for (int base = 0; base < S; base += 2048) {
            const int e0 = base + tid * 8;
            if (e0 + 7 < S) {
                float4 p0 = *reinterpret_cast<const float4*>(p + e0);
                float4 p1 = *reinterpret_cast<const float4*>(p + e0 + 4);
                float4 t0 = *reinterpret_cast<const float4*>(t + e0);
                float4 t1 = *reinterpret_cast<const float4*>(t + e0 + 4);
                float4 ea = *reinterpret_cast<const float4*>(e + e0);
                float4 eb = *reinterpret_cast<const float4*>(e + e0 + 4);

                float pv[8] = {p0.x,p0.y,p0.z,p0.w,p1.x,p1.y,p1.z,p1.w};
                float tv[8] = {t0.x,t0.y,t0.z,t0.w,t1.x,t1.y,t1.z,t1.w};
                float ev[8] = {ea.x,ea.y,ea.z,ea.w,eb.x,eb.y,eb.z,eb.w};

                #pragma unroll
                for (int q = 0; q < 8; q++) {
                    float d = pv[q] - tv[q];
                    v[0] += d * d;
                    if (ev[q] < 0.02f) {
                        v[1] += 1.f; v[2] += ev[q]; v[3] += pv[q];
                        v[4] += ev[q] * pv[q]; v[5] += ev[q] * ev[q];
                    }
                }
                #pragma unroll
                for (int q = 0; q < 7; q++)
                    v[6] += reluf(pv[q] - pv[q + 1]);
                float nxt = __shfl_down_sync(FULL, pv[0], 1);
                if (lane == 31) nxt = (e0 + 8 < S) ? p[e0 + 8] : pv[7]; // => relu 0
                v[6] += reluf(pv[7] - nxt);
            } else if (e0 < S) {
                for (int i = e0; i < S && i < e0 + 8; i++) {
                    float pvv = p[i], tvv = t[i], evv = e[i];
                    float d = pvv - tvv; v[0] += d * d;
                    if (evv < 0.02f) { v[1] += 1.f; v[2] += evv; v[3] += pvv;
                                       v[4] += evv*pvv; v[5] += evv*evv; }
                    if (i < S - 1) v[6] += reluf(pvv - p[i + 1]);
                }
            }
        }

        #pragma unroll
        for (int k = 0; k < 7; k++) {
            #pragma unroll
            for (int off = 16; off > 0; off >>= 1)
                v[k] += __shfl_xor_sync(FULL, v[k], off);
        }
        if (lane == 0) {
            #pragma unroll
            for (int k = 0; k < 7; k++) sh[k][wid] = v[k];
        }

        // scalar select inside warp 0 (register-only, before the bar)
        float wsel = 0.f, Eb = 0.f;
        if (wid == 0) {
            const int mb = __shfl_sync(FULL, mbl, 0);
            Eb   = __shfl_sync(FULL, Ebl, 0);
            wsel = __shfl_sync(FULL, wl, mb & 31);
        }
        __syncthreads();
        if (tid == 0) {
            float r[7];
            #pragma unroll
            for (int k = 0; k < 7; k++) {
                r[k] = 0.f;
                #pragma unroll
                for (int q = 0; q < 8; q++) r[k] += sh[k][q];
            }
            float wmse = (r[0] / (float)S) * wsel;
            float cnt = r[1], Sx = r[2], Sy = r[3], Sxy = r[4], Sxx = r[5];
            float el_err = 0.f, el_valid = 0.f;
            if (cnt >= 2.f) {
                float safe  = fmaxf(cnt, 1.f);
                float eps_m = Sx / safe;
                float sig_m = Sy / safe;
                float cov = Sxy - sig_m * Sx - eps_m * Sy + cnt * eps_m * sig_m;
                float var = Sxx - 2.f * eps_m * Sx + cnt * eps_m * eps_m;
                float et  = Eb * 1000.f;
                el_err   = fabsf(cov / (var + 1e-8f) - et) / (et + 1e-8f);
                el_valid = 1.f;
            }
            g_samp[0][b] = wmse;
            g_samp[1][b] = el_err;
            g_samp[2][b] = el_valid;
            g_samp[3][b] = r[6];
        }
    } else {
        // ------- strip block: screen, deterministic compaction, balanced reduce -------
        __shared__ int   s_mat[MAXB];
        __shared__ float s_sr[MAXB];
        __shared__ float s_temp[MAXB];
        __shared__ int   s_list[STRIP];   // packed: (local_tid<<2)|(t<<1)|s
        __shared__ int   s_wcnt[8];
        __shared__ int   s_wbase[8];
        __shared__ int   s_total;

        const int strip = blockIdx.x - B;
        const int totalPairs = B * B;

        for (int q = tid; q < B; q += 256) {
            s_mat[q]  = mat[q];
            s_sr[q]   = sr[q];
            s_temp[q] = temp[q];
        }
        __syncthreads();

        const int idx = strip * STRIP + tid;
        bool t_ij = false, s_ji = false;
        if (idx < totalPairs) {
            const int i = idx / B;
            const int j = idx - i * B;
            if (i != j) {
                bool sd, td;
                pair_masks(s_mat[i], s_mat[j], s_sr[i], s_sr[j],
                           s_temp[i], s_temp[j], t_ij, sd);
                pair_masks(s_mat[j], s_mat[i], s_sr[j], s_sr[i],
                           s_temp[j], s_temp[i], td, s_ji);
            }
        }
        const bool need = t_ij || s_ji;

        const unsigned bal  = __ballot_sync(FULL, need);
        const int      rank = __popc(bal & ((1u << lane) - 1u));
        if (lane == 0) s_wcnt[wid] = __popc(bal);
        __syncthreads();
        if (tid == 0) {
            int run = 0;
            #pragma unroll
            for (int q = 0; q < 8; q++) { s_wbase[q] = run; run += s_wcnt[q]; }
            s_total = run;
        }
        __syncthreads();
        if (need)
            s_list[s_wbase[wid] + rank] = (tid << 2) | ((int)t_ij << 1) | (int)s_ji;
        __syncthreads();

        const int total = s_total;
        float tsum = 0.f, tcnt = 0.f, ssum = 0.f, scnt = 0.f;
        const int S4 = S >> 2;
        for (int li = wid; li < total; li += 8) {
            const int packed = s_list[li];
            const int pidx   = strip * STRIP + (packed >> 2);
            const int tt     = (packed >> 1) & 1;
            const int ss     = packed & 1;
            const int i = pidx / B;
            const int j = pidx - i * B;

            const float4* si = reinterpret_cast<const float4*>(pred + (size_t)i * S);
            const float4* sj = reinterpret_cast<const float4*>(pred + (size_t)j * S);
            float acc = 0.f;
            #pragma unroll 8
            for (int k = lane; k < S4; k += 32) {
                float4 a = si[k], bq = sj[k];
                acc += reluf(a.x - bq.x) + reluf(a.y - bq.y)
                     + reluf(a.z - bq.z) + reluf(a.w - bq.w);
            }
            #pragma unroll
            for (int off = 16; off > 0; off >>= 1)
                acc += __shfl_xor_sync(FULL, acc, off);
            const float D = acc / (float)S;
            if (tt) { tsum += D; tcnt += 1.f; }
            if (ss) { ssum += D; scnt += 1.f; }
        }

        if (lane == 0) {
            sh[0][wid] = tsum; sh[1][wid] = tcnt;
            sh[2][wid] = ssum; sh[3][wid] = scnt;
        }
        __syncthreads();
        if (tid == 0) {
            float r0 = 0.f, r1 = 0.f, r2 = 0.f, r3 = 0.f;
            #pragma unroll
            for (int q = 0; q < 8; q++) {
                r0 += sh[0][q]; r1 += sh[1][q];
                r2 += sh[2][q]; r3 += sh[3][q];
            }
            g_pairAcc[0][strip] = r0;
            g_pairAcc[1][strip] = r1;
            g_pairAcc[2][strip] = r2;
            g_pairAcc[3][strip] = r3;
        }
    }

    // ============ sync: scoped atomic only (no MEMBAR anywhere) ============
    if (tid == 0) {
        unsigned int vtk = ticket_add_acq_rel(&g_ticket);
        sh_last = (vtk == gridDim.x - 1);
    }
    __syncthreads();
    if (!sh_last) return;

    // ---- last block: sum partials (L2-direct), write scalar ----
    float acc8[8];
    #pragma unroll
    for (int k = 0; k < 8; k++) acc8[k] = 0.f;

    for (int q = tid; q < B; q += 256) {
        acc8[0] += __ldcg(&g_samp[0][q]);
        acc8[1] += __ldcg(&g_samp[1][q]);
        acc8[2] += __ldcg(&g_samp[2][q]);
        acc8[3] += __ldcg(&g_samp[3][q]);
    }
    for (int s = tid; s < nStrips; s += 256) {
        acc8[4] += __ldcg(&g_pairAcc[0][s]);
        acc8[5] += __ldcg(&g_pairAcc[1][s]);
        acc8[6] += __ldcg(&g_pairAcc[2][s]);
        acc8[7] += __ldcg(&g_pairAcc[3][s]);
    }

    #pragma unroll
    for (int k = 0; k < 8; k++) {
        #pragma unroll
        for (int off = 16; off > 0; off >>= 1)
            acc8[k] += __shfl_xor_sync(FULL, acc8[k], off);
    }
    __syncthreads();                 // sh[][] reuse
    if (lane == 0) {
        #pragma unroll
        for (int k = 0; k < 8; k++) sh[k][wid] = acc8[k];
    }
    __syncthreads();
    if (tid == 0) {
        float r[8];
        #pragma unroll
        for (int k = 0; k < 8; k++) {
            r[k] = 0.f;
            #pragma unroll
            for (int q = 0; q < 8; q++) r[k] += sh[k][q];
        }
        float mse_loss  = r[0] / (float)B;
        float elastic   = (r[2] > 0.f) ? r[1] / fmaxf(r[2], 1.f) : 0.f;
        float mono      = r[3] / (float)(B * (S - 1));
        float temp_loss = (r[5] > 0.f) ? r[4] / fmaxf(r[5], 1.f) : 0.f;
        float sr_loss   = (r[7] > 0.f) ? r[6] / fmaxf(r[7], 1.f) : 0.f;
        out[0] = ALPHA * mse_loss + BETA * (elastic + mono + temp_loss + sr_loss);
        g_ticket = 0;   // reset for next graph replay
    }
}

// --------------------------------------------------------------------------
extern "C" void kernel_launch(void* const* d_in, const int* in_sizes, int n_in,
                              void* d_out, int out_size)
{
    const float* pred   = (const float*)d_in[0];
    const float* target = (const float*)d_in[1];
    const int*   matid  = (const int*)  d_in[2];
    const float* strain = (const float*)d_in[3];
    const float* E_GPa  = (const float*)d_in[4];
    const float* temp   = (const float*)d_in[5];
    const float* sr     = (const float*)d_in[6];
    const float* mw     = (const float*)d_in[7];
    float* out = (float*)d_out;

    const int B  = in_sizes[2];         // material_ids count
    const int S  = in_sizes[0] / B;     // pred = B*S
    const int nW = in_sizes[7];         // material_weights count

    const int pairStrips = (B * B + STRIP - 1) / STRIP;   // 64 for B=128
    const int grid       = B + pairStrips;                 // 192 blocks

    fused_kernel<<<grid, 256>>>(pred, target, matid, strain, E_GPa, temp, sr, mw,
                                out, B, S, pairStrips, nW);
}